// round 4
// baseline (speedup 1.0000x reference)
#include <cuda_runtime.h>
#include <math.h>

#define NI 64
#define NJ 64
#define NK 8
#define KEFF 7          // k=0 is the 'none' (zero) primitive -> dropped
#define CI 8            // i-chunk size
#define NCHUNK (NI/CI)  // 8
#define RPC 256         // rows per CTA

// Precomputed W[i][k-1][j] = softmax(alphas[i,j,:])[k] * coeffs[i,j,k]
// k-major-over-j: consecutive j are contiguous -> f32x2 pairs.
__device__ float g_W[NI * KEFF * NJ];

typedef unsigned long long u64;

__device__ __forceinline__ u64 pk2(float v) {
    u64 r; asm("mov.b64 %0, {%1, %1};" : "=l"(r) : "f"(v)); return r;
}
__device__ __forceinline__ void fma2(u64& d, u64 a, u64 b) {
    asm("fma.rn.f32x2 %0, %1, %2, %0;" : "+l"(d) : "l"(a), "l"(b));
}

// ---------------------------------------------------------------------------
// Kernel 1: build W (tiny: 64x64 threads)
// ---------------------------------------------------------------------------
__global__ void build_w_kernel(const float* __restrict__ alphas,
                               const float* __restrict__ coeffs) {
    int i = blockIdx.x;
    int j = threadIdx.x;
    const float* a = alphas + (size_t)(i * NJ + j) * NK;
    const float* c = coeffs + (size_t)(i * NJ + j) * NK;

    float av[NK];
#pragma unroll
    for (int k = 0; k < NK; ++k) av[k] = a[k];
    float mx = av[0];
#pragma unroll
    for (int k = 1; k < NK; ++k) mx = fmaxf(mx, av[k]);
    float e[NK];
    float s = 0.f;
#pragma unroll
    for (int k = 0; k < NK; ++k) { e[k] = __expf(av[k] - mx); s += e[k]; }
    float inv = 1.0f / s;
#pragma unroll
    for (int k = 1; k < NK; ++k)
        g_W[((size_t)i * KEFF + (k - 1)) * NJ + j] = e[k] * inv * c[k];
}

// ---------------------------------------------------------------------------
// Kernel 2: main.
// 256 threads, 256 rows/CTA. i processed in chunks of CI=8.
// Per chunk:
//   - stage W chunk [CI][KEFF][NJ] into smem (14.3 KB)
//   - each thread computes the 7 primitives for ITS row x values ONCE,
//     stores to smem sP[CI][KEFF][RPC] (57.3 KB)  -> kills the 4x MUFU dup
//   - FMA phase: thread = 4 rows x 16 j, all operands from smem.
//     Per (i,k): 1 LDS.128 prims + 4 LDS.128 W (warp-broadcast) + 32 FFMA2.
// FMA pipe is the only heavy consumer -> near the 52us FFMA2 floor.
// ---------------------------------------------------------------------------
__global__ __launch_bounds__(256, 2)
void darts_main_kernel(const float* __restrict__ x,
                       float* __restrict__ out) {
    __shared__ float sP[CI][KEFF][RPC];   // primitives, row-fastest
    __shared__ float sW[CI][KEFF][NJ];    // W chunk, j-fastest

    const int tid = threadIdx.x;
    const int tg  = tid >> 2;        // 0..63  -> rows tg*4 .. tg*4+3
    const int jq  = tid & 3;         // 0..3   -> j block
    const int j0  = jq * 16;
    const int b0  = blockIdx.x * RPC;

    u64 acc[4][8];
#pragma unroll
    for (int r = 0; r < 4; ++r)
#pragma unroll
        for (int q = 0; q < 8; ++q) acc[r][q] = 0ull;

    for (int ic = 0; ic < NCHUNK; ++ic) {
        // ---- stage W chunk (coalesced, float2) ----
        {
            const float2* wsrc = reinterpret_cast<const float2*>(
                g_W + (size_t)ic * CI * KEFF * NJ);
            float2* wdst = reinterpret_cast<float2*>(&sW[0][0][0]);
#pragma unroll
            for (int n = 0; n < (CI * KEFF * NJ / 2) / 256; ++n)
                wdst[n * 256 + tid] = wsrc[n * 256 + tid];
        }
        // ---- compute primitives for row = tid, i in chunk ----
        {
            const float* xr = x + (size_t)(b0 + tid) * NI + ic * CI;
            float4 xa = *reinterpret_cast<const float4*>(xr);
            float4 xb = *reinterpret_cast<const float4*>(xr + 4);
            float xs[CI] = {xa.x, xa.y, xa.z, xa.w, xb.x, xb.y, xb.z, xb.w};
#pragma unroll
            for (int n = 0; n < CI; ++n) {
                float v  = xs[n];
                float v2 = v * v;
                sP[n][0][tid] = v;                     // linear
                sP[n][1][tid] = v2;                    // x^2
                sP[n][2][tid] = v2 * v;                // x^3
                sP[n][3][tid] = __expf(v);             // exp
                sP[n][4][tid] = __logf(v);             // ln
                sP[n][5][tid] = __fdividef(1.0f, v);   // reciprocal
                sP[n][6][tid] = __sinf(v);             // sin
            }
        }
        __syncthreads();

        // ---- FMA phase: everything from smem ----
#pragma unroll 2
        for (int ii = 0; ii < CI; ++ii) {
#pragma unroll
            for (int k = 0; k < KEFF; ++k) {
                float4 pv = *reinterpret_cast<const float4*>(&sP[ii][k][tg * 4]);
                u64 pp[4] = {pk2(pv.x), pk2(pv.y), pk2(pv.z), pk2(pv.w)};
                const ulonglong2* wrow =
                    reinterpret_cast<const ulonglong2*>(&sW[ii][k][j0]);
#pragma unroll
                for (int q2 = 0; q2 < 4; ++q2) {
                    ulonglong2 w2 = wrow[q2];   // 4 consecutive j
#pragma unroll
                    for (int r = 0; r < 4; ++r) {
                        fma2(acc[r][2 * q2 + 0], pp[r], w2.x);
                        fma2(acc[r][2 * q2 + 1], pp[r], w2.y);
                    }
                }
            }
        }
        __syncthreads();   // protect sP/sW before next chunk overwrites
    }

    // ---- store: 4 rows x 16 j, as 16B stores ----
#pragma unroll
    for (int r = 0; r < 4; ++r) {
        float* orow = out + (size_t)(b0 + tg * 4 + r) * NJ + j0;
#pragma unroll
        for (int q = 0; q < 4; ++q) {
            ulonglong2 v;
            v.x = acc[r][2 * q + 0];
            v.y = acc[r][2 * q + 1];
            *reinterpret_cast<ulonglong2*>(orow + 4 * q) = v;
        }
    }
}

// ---------------------------------------------------------------------------
extern "C" void kernel_launch(void* const* d_in, const int* in_sizes, int n_in,
                              void* d_out, int out_size) {
    const float* x      = (const float*)d_in[0];  // [B, 64]
    const float* alphas = (const float*)d_in[1];  // [64, 64, 8]
    const float* coeffs = (const float*)d_in[2];  // [64, 64, 8]
    float* out = (float*)d_out;                   // [B, 64]

    int rows = in_sizes[0] / NI;                  // 65536

    build_w_kernel<<<NI, NJ>>>(alphas, coeffs);
    darts_main_kernel<<<rows / RPC, 256>>>(x, out);
}

// round 9
// speedup vs baseline: 2.4907x; 2.4907x over previous
#include <cuda_runtime.h>
#include <cuda_bf16.h>
#include <cstdint>

#define NI 64
#define NJ 64
#define NK 8
#define KEFF 7
#define KTOT 448            // 64*7
#define MTILE 128
#define THREADS 256
#define CI 16               // i's per chunk
#define CK (CI*KEFF)        // 112 k per chunk
#define NCHUNK 4
#define PSTRIDE 120         // bf16 stride, P plane rows (240B, conflict-free ldmatrix)
#define WSTRIDE 456         // bf16 stride, W^T rows (912B, conflict-free ldmatrix)

// W^T planes in global, [n=64][k=448] bf16 row-major (n-major, k contiguous)
__device__ __align__(16) __nv_bfloat16 g_Wh[NJ * KTOT];
__device__ __align__(16) __nv_bfloat16 g_Wl[NJ * KTOT];

// smem layout (bytes)
#define SM_WH 0
#define SM_WL 58368                       // 64*456*2
#define SM_PH 116736
#define SM_PL 147456                      // + 128*240
#define SM_TOTAL 178176

typedef uint32_t u32;
typedef unsigned long long u64;

__device__ __forceinline__ u32 smem_u32(const void* p) {
    u32 a;
    asm("{ .reg .u64 t; cvta.to.shared.u64 t, %1; cvt.u32.u64 %0, t; }"
        : "=r"(a) : "l"(p));
    return a;
}
__device__ __forceinline__ void ldm4(u32* d, u32 addr) {
    asm volatile("ldmatrix.sync.aligned.m8n8.x4.shared.b16 {%0,%1,%2,%3}, [%4];"
                 : "=r"(d[0]), "=r"(d[1]), "=r"(d[2]), "=r"(d[3]) : "r"(addr));
}
__device__ __forceinline__ void sts128(u32 addr, const u32* v) {
    asm volatile("st.shared.v4.b32 [%0], {%1,%2,%3,%4};"
                 :: "r"(addr), "r"(v[0]), "r"(v[1]), "r"(v[2]), "r"(v[3]) : "memory");
}
__device__ __forceinline__ void mma16816(float* c, const u32* a, u32 b0, u32 b1) {
    asm volatile(
        "mma.sync.aligned.m16n8k16.row.col.f32.bf16.bf16.f32 "
        "{%0,%1,%2,%3}, {%4,%5,%6,%7}, {%8,%9}, {%0,%1,%2,%3};"
        : "+f"(c[0]), "+f"(c[1]), "+f"(c[2]), "+f"(c[3])
        : "r"(a[0]), "r"(a[1]), "r"(a[2]), "r"(a[3]), "r"(b0), "r"(b1));
}
__device__ __forceinline__ u32 pkbf(float even, float odd) {
    __nv_bfloat162 t = __floats2bfloat162_rn(even, odd);  // .x -> low 16 bits
    return *reinterpret_cast<u32*>(&t);
}
__device__ __forceinline__ void prim_hilo(float v, float* hi, float* lo) {
    float p[KEFF];
    float v2 = v * v;
    p[0] = v;
    p[1] = v2;
    p[2] = v2 * v;
    p[3] = __expf(v);
    p[4] = __logf(v);
    p[5] = __fdividef(1.0f, v);
    p[6] = __sinf(v);
#pragma unroll
    for (int m = 0; m < KEFF; ++m) {
        float h = __bfloat162float(__float2bfloat16_rn(p[m]));
        hi[m] = h;
        lo[m] = p[m] - h;
    }
}

// ---------------------------------------------------------------------------
// Kernel 1: W^T hi/lo planes.  W[k=i*7+m][j] = softmax(alphas[i,j,:])[m+1]*coeffs
// stored transposed: g_W*[j*448 + k]
// ---------------------------------------------------------------------------
__global__ void build_w_kernel(const float* __restrict__ alphas,
                               const float* __restrict__ coeffs) {
    int i = blockIdx.x;
    int j = threadIdx.x;
    const float* a = alphas + (size_t)(i * NJ + j) * NK;
    const float* c = coeffs + (size_t)(i * NJ + j) * NK;

    float av[NK];
#pragma unroll
    for (int k = 0; k < NK; ++k) av[k] = a[k];
    float mx = av[0];
#pragma unroll
    for (int k = 1; k < NK; ++k) mx = fmaxf(mx, av[k]);
    float e[NK], s = 0.f;
#pragma unroll
    for (int k = 0; k < NK; ++k) { e[k] = __expf(av[k] - mx); s += e[k]; }
    float inv = 1.0f / s;

#pragma unroll
    for (int m = 0; m < KEFF; ++m) {
        float w = e[m + 1] * inv * c[m + 1];
        int k = i * KEFF + m;
        __nv_bfloat16 h = __float2bfloat16_rn(w);
        float hf = __bfloat162float(h);
        g_Wh[(size_t)j * KTOT + k] = h;
        g_Wl[(size_t)j * KTOT + k] = __float2bfloat16_rn(w - hf);
    }
}

// ---------------------------------------------------------------------------
// Kernel 2: HMMA GEMM via mma.sync.m16n8k16 (bf16 -> fp32).
// CTA = 128 rows, 8 warps; warp w owns rows [16w,16w+16) x all 64 j.
// P chunk planes are written by the SAME warp that consumes them -> syncwarp only.
// ---------------------------------------------------------------------------
__global__ __launch_bounds__(THREADS, 1)
void darts_hmma_kernel(const float* __restrict__ x, float* __restrict__ out) {
    extern __shared__ char smem[];
    const u32 smem_base = smem_u32(smem);
    const int tid  = threadIdx.x;
    const int wid  = tid >> 5;
    const int lane = tid & 31;
    const int b0   = blockIdx.x * MTILE;

    // ---- stage W^T hi+lo into smem with padded stride (coalesced uint4) ----
    {
        const uint4* sh = reinterpret_cast<const uint4*>(g_Wh);
        const uint4* sl = reinterpret_cast<const uint4*>(g_Wl);
#pragma unroll
        for (int n = 0; n < 14; ++n) {               // 3584 uint4 per plane
            int idx = n * THREADS + tid;
            int flat = idx * 8;                      // bf16 units
            int row = flat / KTOT, col = flat % KTOT;
            u32 doff = (u32)(row * (WSTRIDE * 2) + col * 2);
            *reinterpret_cast<uint4*>(smem + SM_WH + doff) = sh[idx];
            *reinterpret_cast<uint4*>(smem + SM_WL + doff) = sl[idx];
        }
    }
    __syncthreads();

    float acc[32];
#pragma unroll
    for (int q = 0; q < 32; ++q) acc[q] = 0.f;

    // invariant ldmatrix lane-address components
    const u32 a_row   = (u32)((wid << 4) + (lane & 7) + ((lane >> 3) & 1) * 8);
    const u32 a_kside = (u32)((lane >> 4) * 8);
    const u32 ab_h = smem_base + SM_PH + a_row * (PSTRIDE * 2) + a_kside * 2;
    const u32 ab_l = smem_base + SM_PL + a_row * (PSTRIDE * 2) + a_kside * 2;
    const u32 b_n     = (u32)((lane & 7) + (lane >> 4) * 8);   // n within 16-group
    const u32 b_kside = (u32)(((lane >> 3) & 1) * 8);

#pragma unroll
    for (int ic = 0; ic < NCHUNK; ++ic) {
        // ---- primitives for this warp's 16 rows x 16 i's ----
        {
            const int r_loc = (wid << 4) + (lane >> 1);
            const int ih = lane & 1;
            const float* xp = x + (size_t)(b0 + r_loc) * NI + ic * CI + ih * 8;
            float4 xa = *reinterpret_cast<const float4*>(xp);
            float4 xb = *reinterpret_cast<const float4*>(xp + 4);
            float xs[8] = {xa.x, xa.y, xa.z, xa.w, xb.x, xb.y, xb.z, xb.w};

            u32 hiP[28], loP[28];
#pragma unroll
            for (int g = 0; g < 4; ++g) {
                float ha[KEFF], la[KEFF], hb[KEFF], lb[KEFF];
                prim_hilo(xs[2 * g],     ha, la);
                prim_hilo(xs[2 * g + 1], hb, lb);
                const int pb = g * 7;
                hiP[pb + 0] = pkbf(ha[0], ha[1]);
                hiP[pb + 1] = pkbf(ha[2], ha[3]);
                hiP[pb + 2] = pkbf(ha[4], ha[5]);
                hiP[pb + 3] = pkbf(ha[6], hb[0]);
                hiP[pb + 4] = pkbf(hb[1], hb[2]);
                hiP[pb + 5] = pkbf(hb[3], hb[4]);
                hiP[pb + 6] = pkbf(hb[5], hb[6]);
                loP[pb + 0] = pkbf(la[0], la[1]);
                loP[pb + 1] = pkbf(la[2], la[3]);
                loP[pb + 2] = pkbf(la[4], la[5]);
                loP[pb + 3] = pkbf(la[6], lb[0]);
                loP[pb + 4] = pkbf(lb[1], lb[2]);
                loP[pb + 5] = pkbf(lb[3], lb[4]);
                loP[pb + 6] = pkbf(lb[5], lb[6]);
            }
            const u32 ph = smem_base + SM_PH + r_loc * (PSTRIDE * 2) + ih * 112;
            const u32 pl = smem_base + SM_PL + r_loc * (PSTRIDE * 2) + ih * 112;
#pragma unroll
            for (int q = 0; q < 7; ++q) {
                sts128(ph + q * 16, hiP + 4 * q);
                sts128(pl + q * 16, loP + 4 * q);
            }
        }
        __syncwarp();

        // ---- 7 k-steps of MMA over this chunk ----
#pragma unroll
        for (int ks = 0; ks < 7; ++ks) {
            u32 ah[4], al[4];
            ldm4(ah, ab_h + ks * 32);
            ldm4(al, ab_l + ks * 32);
            const u32 gk = (u32)(ic * CK + ks * 16) + b_kside;
#pragma unroll
            for (int u = 0; u < 4; ++u) {
                u32 bh[4], bl[4];
                const u32 baddr = smem_base + SM_WH +
                                  (u * 16 + b_n) * (WSTRIDE * 2) + gk * 2;
                ldm4(bh, baddr);
                ldm4(bl, baddr + (SM_WL - SM_WH));
                float* c0 = acc + (2 * u) * 4;
                float* c1 = acc + (2 * u + 1) * 4;
                mma16816(c0, ah, bh[0], bh[1]);
                mma16816(c0, al, bh[0], bh[1]);
                mma16816(c0, ah, bl[0], bl[1]);
                mma16816(c1, ah, bh[2], bh[3]);
                mma16816(c1, al, bh[2], bh[3]);
                mma16816(c1, ah, bl[2], bl[3]);
            }
        }
        __syncwarp();   // all lanes done reading P before next chunk overwrite
    }

    // ---- epilogue: D fragments straight to global ----
    {
        const int row = b0 + (wid << 4) + (lane >> 2);
        const int col = (lane & 3) * 2;
#pragma unroll
        for (int nt = 0; nt < 8; ++nt) {
            float2 v01 = make_float2(acc[nt * 4 + 0], acc[nt * 4 + 1]);
            float2 v23 = make_float2(acc[nt * 4 + 2], acc[nt * 4 + 3]);
            *reinterpret_cast<float2*>(out + (size_t)row * NJ + nt * 8 + col) = v01;
            *reinterpret_cast<float2*>(out + (size_t)(row + 8) * NJ + nt * 8 + col) = v23;
        }
    }
}

// ---------------------------------------------------------------------------
extern "C" void kernel_launch(void* const* d_in, const int* in_sizes, int n_in,
                              void* d_out, int out_size) {
    const float* x      = (const float*)d_in[0];  // [B, 64]
    const float* alphas = (const float*)d_in[1];  // [64, 64, 8]
    const float* coeffs = (const float*)d_in[2];  // [64, 64, 8]
    float* out = (float*)d_out;                   // [B, 64]

    int rows = in_sizes[0] / NI;                  // 65536

    static bool attr_set = false;
    if (!attr_set) {
        cudaFuncSetAttribute(darts_hmma_kernel,
                             cudaFuncAttributeMaxDynamicSharedMemorySize, SM_TOTAL);
        attr_set = true;
    }

    build_w_kernel<<<NI, NJ>>>(alphas, coeffs);
    darts_hmma_kernel<<<rows / MTILE, THREADS, SM_TOTAL>>>(x, out);
}

// round 12
// speedup vs baseline: 3.3303x; 1.3371x over previous
#include <cuda_runtime.h>
#include <cuda_bf16.h>
#include <cstdint>

#define NI 64
#define NJ 64
#define NK 8
#define KEFF 7
#define MTILE 64            // rows per CTA (4 warps x 16)
#define THREADS 128
#define NCHUNK 4
#define KSG 32              // k16 groups (padded K = 512)
#define PSTRIDE 272         // bytes per P row per plane (16-k tiles, conflict-free)

typedef uint32_t u32;

// dense W (fp32), k-major: g_Wd[(i*7+m)*64 + j]
__device__ float g_Wd[448 * NJ];
// W in mma B-fragment order: [ks][u][lane] -> uint4 {b0 n0, b1 n0, b0 n1, b1 n1}
__device__ __align__(16) uint4 g_BfragH[KSG * 4 * 32];
__device__ __align__(16) uint4 g_BfragL[KSG * 4 * 32];

__device__ __forceinline__ u32 smem_u32(const void* p) {
    u32 a;
    asm("{ .reg .u64 t; cvta.to.shared.u64 t, %1; cvt.u32.u64 %0, t; }"
        : "=r"(a) : "l"(p));
    return a;
}
__device__ __forceinline__ void ldm4(u32* d, u32 addr) {
    asm volatile("ldmatrix.sync.aligned.m8n8.x4.shared.b16 {%0,%1,%2,%3}, [%4];"
                 : "=r"(d[0]), "=r"(d[1]), "=r"(d[2]), "=r"(d[3]) : "r"(addr));
}
__device__ __forceinline__ void sts128(u32 addr, const u32* v) {
    asm volatile("st.shared.v4.b32 [%0], {%1,%2,%3,%4};"
                 :: "r"(addr), "r"(v[0]), "r"(v[1]), "r"(v[2]), "r"(v[3]) : "memory");
}
__device__ __forceinline__ void mma16816(float* c, const u32* a, u32 b0, u32 b1) {
    asm volatile(
        "mma.sync.aligned.m16n8k16.row.col.f32.bf16.bf16.f32 "
        "{%0,%1,%2,%3}, {%4,%5,%6,%7}, {%8,%9}, {%0,%1,%2,%3};"
        : "+f"(c[0]), "+f"(c[1]), "+f"(c[2]), "+f"(c[3])
        : "r"(a[0]), "r"(a[1]), "r"(a[2]), "r"(a[3]), "r"(b0), "r"(b1));
}
__device__ __forceinline__ u32 pkbf(float even, float odd) {
    __nv_bfloat162 t = __floats2bfloat162_rn(even, odd);  // .x -> low 16 bits
    return *reinterpret_cast<u32*>(&t);
}
__device__ __forceinline__ void prim_hilo(float v, float* hi, float* lo) {
    float p[KEFF];
    float v2 = v * v;
    p[0] = v;
    p[1] = v2;
    p[2] = v2 * v;
    p[3] = __expf(v);
    p[4] = __logf(v);
    p[5] = __fdividef(1.0f, v);
    p[6] = __sinf(v);
#pragma unroll
    for (int m = 0; m < KEFF; ++m) {
        float h = __bfloat162float(__float2bfloat16_rn(p[m]));
        hi[m] = h;
        lo[m] = p[m] - h;
    }
}

// ---------------------------------------------------------------------------
// Kernel 1a: dense W fp32.  W[k=i*7+m][j] = softmax(alphas[i,j,:])[m+1]*coeffs
// ---------------------------------------------------------------------------
__global__ void build_w_dense(const float* __restrict__ alphas,
                              const float* __restrict__ coeffs) {
    int i = blockIdx.x;
    int j = threadIdx.x;
    const float* a = alphas + (size_t)(i * NJ + j) * NK;
    const float* c = coeffs + (size_t)(i * NJ + j) * NK;

    float av[NK];
#pragma unroll
    for (int k = 0; k < NK; ++k) av[k] = a[k];
    float mx = av[0];
#pragma unroll
    for (int k = 1; k < NK; ++k) mx = fmaxf(mx, av[k]);
    float e[NK], s = 0.f;
#pragma unroll
    for (int k = 0; k < NK; ++k) { e[k] = __expf(av[k] - mx); s += e[k]; }
    float inv = 1.0f / s;
#pragma unroll
    for (int m = 0; m < KEFF; ++m)
        g_Wd[(size_t)(i * KEFF + m) * NJ + j] = e[m + 1] * inv * c[m + 1];
}

// ---------------------------------------------------------------------------
// Kernel 1b: fragment-order W hi/lo.
// k16 group ks holds i = {2ks, 2ks+1} interleaved: pos = 2m + parity(i);
// pos 14,15 are zero pads.  B-frag per PTX m16n8k16 spec (== ldmatrix.x4 output):
//   lane l: t=l&3, g=l>>2, n0=u*16+g, n1=n0+8
//   .x={W[kb+2t][n0],W[kb+2t+1][n0]} .y={W[kb+8+2t][n0],W[kb+9+2t][n0]} .z/.w: n1
// ---------------------------------------------------------------------------
__global__ void build_w_frag() {
    const int ks = blockIdx.x;        // 0..31
    const int u  = blockIdx.y;        // 0..3
    const int lane = threadIdx.x;     // 0..31
    const int t = lane & 3, g = lane >> 2;
    const int n0 = u * 16 + g, n1 = n0 + 8;
    const int pos[4] = {2 * t, 2 * t + 1, 8 + 2 * t, 9 + 2 * t};

    float hv[4][2], lv[4][2];
#pragma unroll
    for (int p = 0; p < 4; ++p) {
        int ps = pos[p];
        float w0 = 0.f, w1 = 0.f;
        if (ps < 14) {
            int i = ks * 2 + (ps & 1);
            int m = ps >> 1;
            int kd = i * KEFF + m;
            w0 = g_Wd[(size_t)kd * NJ + n0];
            w1 = g_Wd[(size_t)kd * NJ + n1];
        }
        float h0 = __bfloat162float(__float2bfloat16_rn(w0));
        float h1 = __bfloat162float(__float2bfloat16_rn(w1));
        hv[p][0] = h0;       hv[p][1] = h1;
        lv[p][0] = w0 - h0;  lv[p][1] = w1 - h1;
    }
    uint4 fh, fl;
    fh.x = pkbf(hv[0][0], hv[1][0]);
    fh.y = pkbf(hv[2][0], hv[3][0]);
    fh.z = pkbf(hv[0][1], hv[1][1]);
    fh.w = pkbf(hv[2][1], hv[3][1]);
    fl.x = pkbf(lv[0][0], lv[1][0]);
    fl.y = pkbf(lv[2][0], lv[3][0]);
    fl.z = pkbf(lv[0][1], lv[1][1]);
    fl.w = pkbf(lv[2][1], lv[3][1]);
    const int idx = (ks * 4 + u) * 32 + lane;
    g_BfragH[idx] = fh;
    g_BfragL[idx] = fl;
}

// ---------------------------------------------------------------------------
// Kernel 2: HMMA GEMM. 128 threads / 4 warps / 64 rows per CTA.
// Warp-private P smem (hi/lo, one 16-i chunk), warp-only sync, W via LDG frags.
// ---------------------------------------------------------------------------
__global__ __launch_bounds__(THREADS, 4)
void darts_hmma_kernel(const float* __restrict__ x, float* __restrict__ out) {
    __shared__ __align__(16) uint8_t sP[4][2][16 * PSTRIDE];  // 34816 B

    const int tid  = threadIdx.x;
    const int w    = tid >> 5;
    const int lane = tid & 31;
    const int b0   = blockIdx.x * MTILE;

    const u32 phb = smem_u32(&sP[w][0][0]);
    const u32 plb = smem_u32(&sP[w][1][0]);

    // ldmatrix A lane address (rows within warp tile, 16-k tiles at ks*32 B)
    const u32 a_row = (u32)((lane & 7) + ((lane >> 3) & 1) * 8);
    const u32 abh = phb + a_row * PSTRIDE + ((lane >> 4) * 8) * 2;
    const u32 abl = plb + a_row * PSTRIDE + ((lane >> 4) * 8) * 2;

    const int prow = lane >> 2;    // 0..7
    const int q    = lane & 3;     // i quarter

    float acc[32];
#pragma unroll
    for (int n = 0; n < 32; ++n) acc[n] = 0.f;

#pragma unroll
    for (int ic = 0; ic < NCHUNK; ++ic) {
        // ---- primitives: 2 passes x (8 rows x 4 i per lane) ----
#pragma unroll
        for (int ps = 0; ps < 2; ++ps) {
            const int row = ps * 8 + prow;
            const float4 xv = *reinterpret_cast<const float4*>(
                x + (size_t)(b0 + w * 16 + row) * NI + ic * 16 + q * 4);
            const float xs[4] = {xv.x, xv.y, xv.z, xv.w};
#pragma unroll
            for (int pp = 0; pp < 2; ++pp) {         // i-pairs (4q+2pp, +1)
                float ha[KEFF], la[KEFF], hb[KEFF], lb[KEFF];
                prim_hilo(xs[2 * pp],     ha, la);
                prim_hilo(xs[2 * pp + 1], hb, lb);
                u32 H[8], L[8];
#pragma unroll
                for (int m = 0; m < KEFF; ++m) {
                    H[m] = pkbf(ha[m], hb[m]);       // pos 2m=even i, 2m+1=odd i
                    L[m] = pkbf(la[m], lb[m]);
                }
                H[7] = 0; L[7] = 0;                  // zero pads (W=0 there)
                const u32 off = (u32)(row * PSTRIDE + (q * 2 + pp) * 32);
                sts128(phb + off, H);
                sts128(phb + off + 16, H + 4);
                sts128(plb + off, L);
                sts128(plb + off + 16, L + 4);
            }
        }
        __syncwarp();

        // ---- 8 k16-steps of MMA ----
#pragma unroll
        for (int ks = 0; ks < 8; ++ks) {
            u32 ah[4], al[4];
            ldm4(ah, abh + ks * 32);
            ldm4(al, abl + ks * 32);
            const int fbase = ((ic * 8 + ks) * 4) * 32 + lane;
#pragma unroll
            for (int u = 0; u < 4; ++u) {
                const uint4 fh = g_BfragH[fbase + u * 32];
                const uint4 fl = g_BfragL[fbase + u * 32];
                float* c0 = acc + (2 * u) * 4;
                float* c1 = acc + (2 * u + 1) * 4;
                mma16816(c0, ah, fh.x, fh.y);
                mma16816(c1, ah, fh.z, fh.w);
                mma16816(c0, al, fh.x, fh.y);
                mma16816(c1, al, fh.z, fh.w);
                mma16816(c0, ah, fl.x, fl.y);
                mma16816(c1, ah, fl.z, fl.w);
            }
        }
        __syncwarp();   // done reading P before next chunk overwrites
    }

    // ---- epilogue: fragments straight to global ----
    {
        const int row = b0 + (w << 4) + (lane >> 2);
        const int col = (lane & 3) * 2;
#pragma unroll
        for (int nt = 0; nt < 8; ++nt) {
            float2 v01 = make_float2(acc[nt * 4 + 0], acc[nt * 4 + 1]);
            float2 v23 = make_float2(acc[nt * 4 + 2], acc[nt * 4 + 3]);
            *reinterpret_cast<float2*>(out + (size_t)row * NJ + nt * 8 + col) = v01;
            *reinterpret_cast<float2*>(out + (size_t)(row + 8) * NJ + nt * 8 + col) = v23;
        }
    }
}

// ---------------------------------------------------------------------------
extern "C" void kernel_launch(void* const* d_in, const int* in_sizes, int n_in,
                              void* d_out, int out_size) {
    const float* x      = (const float*)d_in[0];  // [B, 64]
    const float* alphas = (const float*)d_in[1];  // [64, 64, 8]
    const float* coeffs = (const float*)d_in[2];  // [64, 64, 8]
    float* out = (float*)d_out;                   // [B, 64]

    int rows = in_sizes[0] / NI;                  // 65536

    build_w_dense<<<NI, NJ>>>(alphas, coeffs);
    build_w_frag<<<dim3(KSG, 4), 32>>>();
    darts_hmma_kernel<<<rows / MTILE, THREADS>>>(x, out);
}

// round 13
// speedup vs baseline: 3.5722x; 1.0726x over previous
#include <cuda_runtime.h>
#include <cuda_fp16.h>
#include <cstdint>

#define NI 64
#define NJ 64
#define NK 8
#define KEFF 7
#define KTOT 448            // 64*7, = 28 exact k16 groups (no padding)
#define KSGT 28
#define MTILE 64            // rows per CTA (4 warps x 16)
#define THREADS 128
#define NCHUNK 4            // 4 chunks x 7 k16-steps (16 i each)
#define PSTRIDE 240         // bytes per P row per chunk (224B data + 16 pad)

typedef uint32_t u32;

// W in mma B-fragment order: [ks][u][lane] -> uint4, fp16x2 packed
// fh = hi(W), fl = W - hi(W)  (lo corrects W rounding; P rounding ~2^-12 dominates)
__device__ __align__(16) uint4 g_BfragH[KSGT * 4 * 32];
__device__ __align__(16) uint4 g_BfragL[KSGT * 4 * 32];

__device__ __forceinline__ u32 smem_u32(const void* p) {
    u32 a;
    asm("{ .reg .u64 t; cvta.to.shared.u64 t, %1; cvt.u32.u64 %0, t; }"
        : "=r"(a) : "l"(p));
    return a;
}
__device__ __forceinline__ void ldm4(u32* d, u32 addr) {
    asm volatile("ldmatrix.sync.aligned.m8n8.x4.shared.b16 {%0,%1,%2,%3}, [%4];"
                 : "=r"(d[0]), "=r"(d[1]), "=r"(d[2]), "=r"(d[3]) : "r"(addr));
}
__device__ __forceinline__ void sts64(u32 addr, u32 v0, u32 v1) {
    asm volatile("st.shared.v2.b32 [%0], {%1,%2};"
                 :: "r"(addr), "r"(v0), "r"(v1) : "memory");
}
__device__ __forceinline__ void mma16816(float* c, const u32* a, u32 b0, u32 b1) {
    asm volatile(
        "mma.sync.aligned.m16n8k16.row.col.f32.f16.f16.f32 "
        "{%0,%1,%2,%3}, {%4,%5,%6,%7}, {%8,%9}, {%0,%1,%2,%3};"
        : "+f"(c[0]), "+f"(c[1]), "+f"(c[2]), "+f"(c[3])
        : "r"(a[0]), "r"(a[1]), "r"(a[2]), "r"(a[3]), "r"(b0), "r"(b1));
}
__device__ __forceinline__ u32 pkh(float even, float odd) {
    __half2 t = __floats2half2_rn(even, odd);   // .x -> low 16 bits (k even)
    return *reinterpret_cast<u32*>(&t);
}
__device__ __forceinline__ void prim7(float v, float* p) {
    float v2 = v * v;
    p[0] = v;
    p[1] = v2;
    p[2] = v2 * v;
    p[3] = __expf(v);
    p[4] = __logf(v);
    p[5] = __fdividef(1.0f, v);
    p[6] = __sinf(v);
}

// ---------------------------------------------------------------------------
// Kernel 1 (merged prep, single CTA): dense W in smem, then fragment planes.
// W[k=i*7+m][j] = softmax(alphas[i,j,:])[m+1] * coeffs[i,j,m+1]
// B-frag mapping (verified in R12): lane l: t=l&3, g=l>>2, n0=u*16+g, n1=n0+8,
// pos={2t,2t+1,8+2t,9+2t}, k=16ks+pos;
// fh.x=(pos0,pos1)@n0 fh.y=(pos2,pos3)@n0 fh.z/.w same @n1.
// ---------------------------------------------------------------------------
__global__ void build_w_all(const float* __restrict__ alphas,
                            const float* __restrict__ coeffs) {
    extern __shared__ float wsm[];   // [448][64] fp32 = 114688 B
    const int tid = threadIdx.x;     // 1024 threads

    for (int e = tid; e < NI * NJ; e += 1024) {
        const int i = e >> 6, j = e & 63;
        const float* a = alphas + (size_t)(i * NJ + j) * NK;
        const float* c = coeffs + (size_t)(i * NJ + j) * NK;
        float av[NK];
#pragma unroll
        for (int k = 0; k < NK; ++k) av[k] = a[k];
        float mx = av[0];
#pragma unroll
        for (int k = 1; k < NK; ++k) mx = fmaxf(mx, av[k]);
        float ex[NK], s = 0.f;
#pragma unroll
        for (int k = 0; k < NK; ++k) { ex[k] = __expf(av[k] - mx); s += ex[k]; }
        float inv = 1.0f / s;
#pragma unroll
        for (int m = 0; m < KEFF; ++m)
            wsm[(i * KEFF + m) * NJ + j] = ex[m + 1] * inv * c[m + 1];
    }
    __syncthreads();

    for (int e = tid; e < KSGT * 4 * 32; e += 1024) {
        const int lane = e & 31;
        const int u    = (e >> 5) & 3;
        const int ks   = e >> 7;
        const int t = lane & 3, g = lane >> 2;
        const int n0 = u * 16 + g, n1 = n0 + 8;
        const int pos[4] = {2 * t, 2 * t + 1, 8 + 2 * t, 9 + 2 * t};

        float hv[4][2], lv[4][2];
#pragma unroll
        for (int p = 0; p < 4; ++p) {
            const int k = 16 * ks + pos[p];
            float w0 = wsm[k * NJ + n0];
            float w1 = wsm[k * NJ + n1];
            float h0 = __half2float(__float2half_rn(w0));
            float h1 = __half2float(__float2half_rn(w1));
            hv[p][0] = h0;       hv[p][1] = h1;
            lv[p][0] = w0 - h0;  lv[p][1] = w1 - h1;
        }
        uint4 fh, fl;
        fh.x = pkh(hv[0][0], hv[1][0]);
        fh.y = pkh(hv[2][0], hv[3][0]);
        fh.z = pkh(hv[0][1], hv[1][1]);
        fh.w = pkh(hv[2][1], hv[3][1]);
        fl.x = pkh(lv[0][0], lv[1][0]);
        fl.y = pkh(lv[2][0], lv[3][0]);
        fl.z = pkh(lv[0][1], lv[1][1]);
        fl.w = pkh(lv[2][1], lv[3][1]);
        g_BfragH[e] = fh;
        g_BfragL[e] = fl;
    }
}

// ---------------------------------------------------------------------------
// Kernel 2: HMMA GEMM, fp16 P (single plane) x fp16 W (hi+lo planes via LDG).
// 128 threads / 4 warps / 64 rows per CTA; warp-private P smem; warp-only sync.
// ---------------------------------------------------------------------------
__global__ __launch_bounds__(THREADS, 4)
void darts_hmma_kernel(const float* __restrict__ x, float* __restrict__ out) {
    __shared__ __align__(16) uint8_t sP[4][16 * PSTRIDE];   // 15360 B

    const int tid  = threadIdx.x;
    const int w    = tid >> 5;
    const int lane = tid & 31;
    const int b0   = blockIdx.x * MTILE;

    const u32 pb = smem_u32(&sP[w][0]);

    // ldmatrix A lane address (16 rows x 16 k per step, 32B per k16 tile)
    const u32 a_row = (u32)((lane & 7) + ((lane >> 3) & 1) * 8);
    const u32 ab = pb + a_row * PSTRIDE + ((lane >> 4) * 8) * 2;

    const int prow = lane >> 2;    // 0..7
    const int q    = lane & 3;     // i quarter (4 i's)

    float acc[32];
#pragma unroll
    for (int n = 0; n < 32; ++n) acc[n] = 0.f;

#pragma unroll
    for (int ic = 0; ic < NCHUNK; ++ic) {
        // ---- primitives: 2 passes x (8 rows x 4 i per lane), fp16 pack ----
#pragma unroll
        for (int ps = 0; ps < 2; ++ps) {
            const int row = ps * 8 + prow;
            const float4 xv = *reinterpret_cast<const float4*>(
                x + (size_t)(b0 + w * 16 + row) * NI + ic * 16 + q * 4);

            float pa[KEFF], pc[KEFF], pd[KEFF], pe[KEFF];
            prim7(xv.x, pa);
            prim7(xv.y, pc);
            prim7(xv.z, pd);
            prim7(xv.w, pe);

            u32 W14[14];
            W14[0]  = pkh(pa[0], pa[1]);
            W14[1]  = pkh(pa[2], pa[3]);
            W14[2]  = pkh(pa[4], pa[5]);
            W14[3]  = pkh(pa[6], pc[0]);
            W14[4]  = pkh(pc[1], pc[2]);
            W14[5]  = pkh(pc[3], pc[4]);
            W14[6]  = pkh(pc[5], pc[6]);
            W14[7]  = pkh(pd[0], pd[1]);
            W14[8]  = pkh(pd[2], pd[3]);
            W14[9]  = pkh(pd[4], pd[5]);
            W14[10] = pkh(pd[6], pe[0]);
            W14[11] = pkh(pe[1], pe[2]);
            W14[12] = pkh(pe[3], pe[4]);
            W14[13] = pkh(pe[5], pe[6]);

            const u32 base = pb + (u32)(row * PSTRIDE + q * 56);
#pragma unroll
            for (int s = 0; s < 7; ++s)
                sts64(base + s * 8, W14[2 * s], W14[2 * s + 1]);
        }
        __syncwarp();

        // ---- 7 k16-steps of MMA over this chunk ----
#pragma unroll
        for (int ks = 0; ks < 7; ++ks) {
            u32 a4[4];
            ldm4(a4, ab + ks * 32);
            const int fbase = ((ic * 7 + ks) * 4) * 32 + lane;
#pragma unroll
            for (int u = 0; u < 4; ++u) {
                const uint4 fh = g_BfragH[fbase + u * 32];
                const uint4 fl = g_BfragL[fbase + u * 32];
                float* c0 = acc + (2 * u) * 4;
                float* c1 = acc + (2 * u + 1) * 4;
                mma16816(c0, a4, fh.x, fh.y);
                mma16816(c1, a4, fh.z, fh.w);
                mma16816(c0, a4, fl.x, fl.y);
                mma16816(c1, a4, fl.z, fl.w);
            }
        }
        __syncwarp();   // done reading P before next chunk overwrites
    }

    // ---- epilogue: fragments straight to global ----
    {
        const int row = b0 + (w << 4) + (lane >> 2);
        const int col = (lane & 3) * 2;
#pragma unroll
        for (int nt = 0; nt < 8; ++nt) {
            float2 v01 = make_float2(acc[nt * 4 + 0], acc[nt * 4 + 1]);
            float2 v23 = make_float2(acc[nt * 4 + 2], acc[nt * 4 + 3]);
            *reinterpret_cast<float2*>(out + (size_t)row * NJ + nt * 8 + col) = v01;
            *reinterpret_cast<float2*>(out + (size_t)(row + 8) * NJ + nt * 8 + col) = v23;
        }
    }
}

// ---------------------------------------------------------------------------
extern "C" void kernel_launch(void* const* d_in, const int* in_sizes, int n_in,
                              void* d_out, int out_size) {
    const float* x      = (const float*)d_in[0];  // [B, 64]
    const float* alphas = (const float*)d_in[1];  // [64, 64, 8]
    const float* coeffs = (const float*)d_in[2];  // [64, 64, 8]
    float* out = (float*)d_out;                   // [B, 64]

    int rows = in_sizes[0] / NI;                  // 65536

    static bool attr_set = false;
    if (!attr_set) {
        cudaFuncSetAttribute(build_w_all,
                             cudaFuncAttributeMaxDynamicSharedMemorySize,
                             KTOT * NJ * (int)sizeof(float));
        attr_set = true;
    }

    build_w_all<<<1, 1024, KTOT * NJ * sizeof(float)>>>(alphas, coeffs);
    darts_hmma_kernel<<<rows / MTILE, THREADS>>>(x, out);
}

// round 17
// speedup vs baseline: 5.5884x; 1.5644x over previous
#include <cuda_runtime.h>
#include <cuda_fp16.h>
#include <cstdint>

#define NI 64
#define NJ 64
#define NK 8
#define KEFF 7
#define KTOT 448            // 64*7 = 28 exact k16 groups (no padding)
#define KSGT 28
#define MTILE 128           // rows per CTA (4 warps x 32)
#define THREADS 128
#define NCHUNK 4            // 4 chunks x 7 k16-steps (16 i each)
#define PSTRIDE 240         // bytes per P row per chunk (224B data + 16 pad)

typedef uint32_t u32;

// W (fp16, single plane) in mma B-fragment order:
// [ks][u][lane] -> uint4 {(pos0,pos1)@n0, (pos2,pos3)@n0, (pos0,pos1)@n1, (pos2,pos3)@n1}
__device__ __align__(16) uint4 g_Bfrag[KSGT * 4 * 32];

__device__ __forceinline__ u32 smem_u32(const void* p) {
    u32 a;
    asm("{ .reg .u64 t; cvta.to.shared.u64 t, %1; cvt.u32.u64 %0, t; }"
        : "=r"(a) : "l"(p));
    return a;
}
__device__ __forceinline__ void ldm4(u32* d, u32 addr) {
    asm volatile("ldmatrix.sync.aligned.m8n8.x4.shared.b16 {%0,%1,%2,%3}, [%4];"
                 : "=r"(d[0]), "=r"(d[1]), "=r"(d[2]), "=r"(d[3]) : "r"(addr));
}
__device__ __forceinline__ void sts64(u32 addr, u32 v0, u32 v1) {
    asm volatile("st.shared.v2.b32 [%0], {%1,%2};"
                 :: "r"(addr), "r"(v0), "r"(v1) : "memory");
}
__device__ __forceinline__ void mma16816(float* c, const u32* a, u32 b0, u32 b1) {
    asm volatile(
        "mma.sync.aligned.m16n8k16.row.col.f32.f16.f16.f32 "
        "{%0,%1,%2,%3}, {%4,%5,%6,%7}, {%8,%9}, {%0,%1,%2,%3};"
        : "+f"(c[0]), "+f"(c[1]), "+f"(c[2]), "+f"(c[3])
        : "r"(a[0]), "r"(a[1]), "r"(a[2]), "r"(a[3]), "r"(b0), "r"(b1));
}
__device__ __forceinline__ u32 pkh(float even, float odd) {
    __half2 t = __floats2half2_rn(even, odd);   // .x -> low 16 bits (k even)
    return *reinterpret_cast<u32*>(&t);
}
__device__ __forceinline__ void prim7(float v, float* p) {
    float v2 = v * v;
    p[0] = v;
    p[1] = v2;
    p[2] = v2 * v;
    p[3] = __expf(v);
    p[4] = __logf(v);
    p[5] = __fdividef(1.0f, v);
    p[6] = __sinf(v);
}

// ---------------------------------------------------------------------------
// Kernel 1: direct fragment build. 28 blocks (one per k16 group) x 128 threads.
// Each thread owns one (u, lane) fragment slot = 8 W values; computes the
// needed softmaxes directly (8-wide, redundancy is cheap and fully parallel).
// W[k=i*7+m][j] = softmax(alphas[i,j,:])[m+1] * coeffs[i,j,m+1]
// ---------------------------------------------------------------------------
__device__ __forceinline__ float w_val(const float* __restrict__ alphas,
                                       const float* __restrict__ coeffs,
                                       int i, int j, int m) {
    const float* a = alphas + (size_t)(i * NJ + j) * NK;
    float av[NK];
#pragma unroll
    for (int k = 0; k < NK; ++k) av[k] = a[k];
    float mx = av[0];
#pragma unroll
    for (int k = 1; k < NK; ++k) mx = fmaxf(mx, av[k]);
    float ex[NK], s = 0.f;
#pragma unroll
    for (int k = 0; k < NK; ++k) { ex[k] = __expf(av[k] - mx); s += ex[k]; }
    return ex[m + 1] / s * coeffs[(size_t)(i * NJ + j) * NK + (m + 1)];
}

__global__ void build_w_frag(const float* __restrict__ alphas,
                             const float* __restrict__ coeffs) {
    const int ks   = blockIdx.x;          // 0..27
    const int lane = threadIdx.x & 31;
    const int u    = threadIdx.x >> 5;    // 0..3
    const int t = lane & 3, g = lane >> 2;
    const int n0 = u * 16 + g, n1 = n0 + 8;
    const int pos[4] = {2 * t, 2 * t + 1, 8 + 2 * t, 9 + 2 * t};

    float v0[4], v1[4];
#pragma unroll
    for (int p = 0; p < 4; ++p) {
        const int k = 16 * ks + pos[p];
        const int i = k / KEFF, m = k % KEFF;
        v0[p] = w_val(alphas, coeffs, i, n0, m);
        v1[p] = w_val(alphas, coeffs, i, n1, m);
    }
    uint4 f;
    f.x = pkh(v0[0], v0[1]);
    f.y = pkh(v0[2], v0[3]);
    f.z = pkh(v1[0], v1[1]);
    f.w = pkh(v1[2], v1[3]);
    g_Bfrag[(ks * 4 + u) * 32 + lane] = f;
}

// ---------------------------------------------------------------------------
// Kernel 2: HMMA GEMM, fp16 x fp16 -> fp32. 128 threads / 4 warps.
// Warp = 32 rows (two 16-row A tiles sharing every B fragment).
// Warp-private P smem, warp-only sync, W via coalesced LDG fragments.
// ---------------------------------------------------------------------------
__global__ __launch_bounds__(THREADS, 3)
void darts_hmma_kernel(const float* __restrict__ x, float* __restrict__ out) {
    __shared__ __align__(16) uint8_t sP[4][32 * PSTRIDE];   // 30720 B

    const int tid  = threadIdx.x;
    const int w    = tid >> 5;
    const int lane = tid & 31;
    const int b0   = blockIdx.x * MTILE;

    const u32 pb = smem_u32(&sP[w][0]);

    // ldmatrix A lane addresses for the two 16-row tiles
    const u32 a_row = (u32)((lane & 7) + ((lane >> 3) & 1) * 8);
    const u32 ab0 = pb + a_row * PSTRIDE + ((lane >> 4) * 8) * 2;
    const u32 ab1 = ab0 + 16 * PSTRIDE;

    const int prow = lane >> 2;    // 0..7
    const int q    = lane & 3;     // i quarter (4 i's)

    float acc[2][32];
#pragma unroll
    for (int tI = 0; tI < 2; ++tI)
#pragma unroll
        for (int n = 0; n < 32; ++n) acc[tI][n] = 0.f;

#pragma unroll
    for (int ic = 0; ic < NCHUNK; ++ic) {
        // ---- primitives: 4 passes x (8 rows x 4 i per lane), fp16 pack ----
#pragma unroll
        for (int ps = 0; ps < 4; ++ps) {
            const int row = ps * 8 + prow;
            const float4 xv = *reinterpret_cast<const float4*>(
                x + (size_t)(b0 + w * 32 + row) * NI + ic * 16 + q * 4);

            float pa[KEFF], pc[KEFF], pd[KEFF], pe[KEFF];
            prim7(xv.x, pa);
            prim7(xv.y, pc);
            prim7(xv.z, pd);
            prim7(xv.w, pe);

            u32 W14[14];
            W14[0]  = pkh(pa[0], pa[1]);
            W14[1]  = pkh(pa[2], pa[3]);
            W14[2]  = pkh(pa[4], pa[5]);
            W14[3]  = pkh(pa[6], pc[0]);
            W14[4]  = pkh(pc[1], pc[2]);
            W14[5]  = pkh(pc[3], pc[4]);
            W14[6]  = pkh(pc[5], pc[6]);
            W14[7]  = pkh(pd[0], pd[1]);
            W14[8]  = pkh(pd[2], pd[3]);
            W14[9]  = pkh(pd[4], pd[5]);
            W14[10] = pkh(pd[6], pe[0]);
            W14[11] = pkh(pe[1], pe[2]);
            W14[12] = pkh(pe[3], pe[4]);
            W14[13] = pkh(pe[5], pe[6]);

            const u32 base = pb + (u32)(row * PSTRIDE + q * 56);
#pragma unroll
            for (int s = 0; s < 7; ++s)
                sts64(base + s * 8, W14[2 * s], W14[2 * s + 1]);
        }
        __syncwarp();

        // ---- 7 k16-steps of MMA over this chunk ----
#pragma unroll
        for (int ks = 0; ks < 7; ++ks) {
            u32 a0[4], a1[4];
            ldm4(a0, ab0 + ks * 32);
            ldm4(a1, ab1 + ks * 32);
            const int fbase = ((ic * 7 + ks) * 4) * 32 + lane;
#pragma unroll
            for (int u = 0; u < 4; ++u) {
                const uint4 f = g_Bfrag[fbase + u * 32];
                mma16816(acc[0] + (2 * u) * 4,     a0, f.x, f.y);
                mma16816(acc[0] + (2 * u + 1) * 4, a0, f.z, f.w);
                mma16816(acc[1] + (2 * u) * 4,     a1, f.x, f.y);
                mma16816(acc[1] + (2 * u + 1) * 4, a1, f.z, f.w);
            }
        }
        __syncwarp();   // done reading P before next chunk overwrites
    }

    // ---- epilogue: fragments straight to global ----
#pragma unroll
    for (int tI = 0; tI < 2; ++tI) {
        const int row = b0 + (w << 5) + tI * 16 + (lane >> 2);
        const int col = (lane & 3) * 2;
#pragma unroll
        for (int nt = 0; nt < 8; ++nt) {
            float2 v01 = make_float2(acc[tI][nt * 4 + 0], acc[tI][nt * 4 + 1]);
            float2 v23 = make_float2(acc[tI][nt * 4 + 2], acc[tI][nt * 4 + 3]);
            *reinterpret_cast<float2*>(out + (size_t)row * NJ + nt * 8 + col) = v01;
            *reinterpret_cast<float2*>(out + (size_t)(row + 8) * NJ + nt * 8 + col) = v23;
        }
    }
}

// ---------------------------------------------------------------------------
extern "C" void kernel_launch(void* const* d_in, const int* in_sizes, int n_in,
                              void* d_out, int out_size) {
    const float* x      = (const float*)d_in[0];  // [B, 64]
    const float* alphas = (const float*)d_in[1];  // [64, 64, 8]
    const float* coeffs = (const float*)d_in[2];  // [64, 64, 8]
    float* out = (float*)d_out;                   // [B, 64]

    int rows = in_sizes[0] / NI;                  // 65536

    build_w_frag<<<KSGT, THREADS>>>(alphas, coeffs);
    darts_hmma_kernel<<<rows / MTILE, THREADS>>>(x, out);
}